// round 13
// baseline (speedup 1.0000x reference)
#include <cuda_runtime.h>
#include <cuda_fp16.h>
#include <math.h>

#define B_    32
#define N_    512
#define H_    8
#define ACT_  4
#define ALPHA_ 0.2f

typedef unsigned long long ull;

// ---- packed f32x2 helpers (sm_100+) ----
__device__ __forceinline__ ull ffma2(ull a, ull b, ull c) {
    ull d; asm("fma.rn.f32x2 %0, %1, %2, %3;" : "=l"(d) : "l"(a), "l"(b), "l"(c)); return d;
}
__device__ __forceinline__ ull add2(ull a, ull b) {
    ull d; asm("add.rn.f32x2 %0, %1, %2;" : "=l"(d) : "l"(a), "l"(b)); return d;
}
__device__ __forceinline__ ull pack2(float lo, float hi) {
    ull r; asm("mov.b64 %0, {%1,%2};" : "=l"(r) : "f"(lo), "f"(hi)); return r;
}
__device__ __forceinline__ void unpack2(ull v, float& lo, float& hi) {
    asm("mov.b64 {%0,%1}, %2;" : "=f"(lo), "=f"(hi) : "l"(v));
}
__device__ __forceinline__ float pair_sum(ull v) {
    float lo, hi; unpack2(v, lo, hi); return lo + hi;
}

// ---------------- device scratch ----------------
__device__ float g_Wh  [B_*H_*N_*64];
__device__ float g_ssrc[B_*H_*N_];
__device__ float g_sdst[B_*H_*N_];
__device__ float g_x   [B_*N_*H_*64];
__device__ float g_Wh2 [B_*N_*64];
__device__ float g_s2s [B_*N_];
__device__ float g_s2d [B_*N_];
__device__ float g_h2  [B_*N_*64];
__device__ float g_z1p [32*B_*256];
// attend tables: 256 groups x 513 rows x 64 ch
__device__ float g_tabS[256*513*64];   // SufP
__device__ float g_tabQ[256*513*64];   // PreQ
__device__ float2 g_coef[256*512];     // (aC, bC) per query
__device__ int    g_kqg [256*512];     // split point per query

// =====================================================================
// GEMM (16*RPT)-row x 64-col tile, LDS.128 k-quads + ffma2,
// + per-row dots with aSrc/aDst.
// =====================================================================
template<int RPT>
__global__ void gemm_s_kernel(const float* __restrict__ A,
                              const float* __restrict__ Ball,
                              const float* __restrict__ aSrc,
                              const float* __restrict__ aDst,
                              float* __restrict__ Cout,
                              float* __restrict__ sSrc,
                              float* __restrict__ sDst,
                              int K, int outBatch, int outHead, int sBatch)
{
    constexpr int ROWS = 16*RPT;
    __shared__ float As[ROWS*64];
    __shared__ float Bst[64*68];

    int tid = threadIdx.x;            // 256
    int r0  = blockIdx.x * ROWS;
    int h   = blockIdx.y;
    int b   = r0 / N_;
    int n0  = r0 % N_;
    const float* Bmat = Ball + (size_t)h*K*64;

    int tr = tid >> 4;
    int tc = tid & 15;

    ull acc[RPT][4];
#pragma unroll
    for (int i = 0; i < RPT; i++)
#pragma unroll
        for (int j = 0; j < 4; j++) acc[i][j] = 0ull;

    for (int k0 = 0; k0 < K; k0 += 64) {
#pragma unroll
        for (int t = 0; t < RPT*4; t++) {
            int lin = t*256 + tid;
            int row = lin >> 6, kk = lin & 63;
            As[row*64 + kk] = A[(size_t)(r0+row)*K + k0 + kk];
        }
#pragma unroll
        for (int t = 0; t < 16; t++) {
            int lin = t*256 + tid;
            int kk = lin >> 6, o = lin & 63;
            Bst[o*68 + kk] = Bmat[(size_t)(k0+kk)*64 + o];
        }
        __syncthreads();
#pragma unroll 2
        for (int kq = 0; kq < 16; kq++) {
            ulonglong2 b0 = *(const ulonglong2*)&Bst[(tc     )*68 + 4*kq];
            ulonglong2 b1 = *(const ulonglong2*)&Bst[(tc + 16)*68 + 4*kq];
            ulonglong2 b2 = *(const ulonglong2*)&Bst[(tc + 32)*68 + 4*kq];
            ulonglong2 b3 = *(const ulonglong2*)&Bst[(tc + 48)*68 + 4*kq];
#pragma unroll
            for (int i = 0; i < RPT; i++) {
                ulonglong2 av = *(const ulonglong2*)&As[(tr*RPT+i)*64 + 4*kq];
                acc[i][0] = ffma2(av.x, b0.x, acc[i][0]);
                acc[i][1] = ffma2(av.x, b1.x, acc[i][1]);
                acc[i][2] = ffma2(av.x, b2.x, acc[i][2]);
                acc[i][3] = ffma2(av.x, b3.x, acc[i][3]);
                acc[i][0] = ffma2(av.y, b0.y, acc[i][0]);
                acc[i][1] = ffma2(av.y, b1.y, acc[i][1]);
                acc[i][2] = ffma2(av.y, b2.y, acc[i][2]);
                acc[i][3] = ffma2(av.y, b3.y, acc[i][3]);
            }
        }
        __syncthreads();
    }

    float c[RPT][4];
#pragma unroll
    for (int i = 0; i < RPT; i++)
#pragma unroll
        for (int j = 0; j < 4; j++) c[i][j] = pair_sum(acc[i][j]);

    float* outP = Cout + (size_t)b*outBatch + (size_t)h*outHead + (size_t)n0*64;
#pragma unroll
    for (int i = 0; i < RPT; i++) {
        int row = tr*RPT + i;
        outP[(size_t)row*64 + tc     ] = c[i][0];
        outP[(size_t)row*64 + tc + 16] = c[i][1];
        outP[(size_t)row*64 + tc + 32] = c[i][2];
        outP[(size_t)row*64 + tc + 48] = c[i][3];
    }

    const float* aS = aSrc + (size_t)h*64;
    const float* aD = aDst + (size_t)h*64;
    float aSv[4], aDv[4];
#pragma unroll
    for (int j = 0; j < 4; j++) {
        aSv[j] = __ldg(&aS[tc + 16*j]);
        aDv[j] = __ldg(&aD[tc + 16*j]);
    }
#pragma unroll
    for (int i = 0; i < RPT; i++) {
        float ss = c[i][0]*aSv[0] + c[i][1]*aSv[1] + c[i][2]*aSv[2] + c[i][3]*aSv[3];
        float sd = c[i][0]*aDv[0] + c[i][1]*aDv[1] + c[i][2]*aDv[2] + c[i][3]*aDv[3];
#pragma unroll
        for (int off = 8; off > 0; off >>= 1) {
            ss += __shfl_down_sync(0xffffffffu, ss, off, 16);
            sd += __shfl_down_sync(0xffffffffu, sd, off, 16);
        }
        if (tc == 0) {
            int n = n0 + tr*RPT + i;
            sSrc[(size_t)b*sBatch + (size_t)h*N_ + n] = ss;
            sDst[(size_t)b*sBatch + (size_t)h*N_ + n] = sd;
        }
    }
}

// =====================================================================
// attend_pre: sort + scans + per-query coefs + FULL SufP/PreQ tables.
// One block (512 thr) per group (b,h). Writes tables to global.
// =====================================================================
struct AttSmem {
    __half2 Whp[512*32];               // 64 KB
    ull p2[512], q2[512];              // 8 KB
    ull cP2[33*32], cQ2[33*32];        // 16.5 KB
    float sdp[512], ss[512], Pp[512], Pq[512];
    int   perm[512];
    float wtP[16], wtQ[16];
};

__global__ void attend_pre(const float* __restrict__ Wh,
                           const float* __restrict__ sS,
                           const float* __restrict__ sD)
{
    extern __shared__ char smraw[];
    AttSmem& s = *reinterpret_cast<AttSmem*>(smraw);
    int tid  = threadIdx.x;            // 512
    int lane = tid & 31, wid = tid >> 5;
    int g = blockIdx.x;
    const float* WhG = Wh + (size_t)g*512*64;

    float key = sD[(size_t)g*512 + tid];
    int   val = tid;
    s.ss[tid] = sS[(size_t)g*512 + tid];

    // ---- bitonic sort ascending ----
    for (int k = 2; k <= 512; k <<= 1) {
        int j = k >> 1;
        for (; j >= 32; j >>= 1) {
            s.sdp[tid] = key; s.perm[tid] = val;
            __syncthreads();
            float ok = s.sdp[tid ^ j];
            int   ov = s.perm[tid ^ j];
            __syncthreads();
            bool keepMin = ((tid & k) == 0) == ((tid & j) == 0);
            bool take = keepMin ? (ok < key) : (ok > key);
            if (take) { key = ok; val = ov; }
        }
        for (; j >= 1; j >>= 1) {
            float ok = __shfl_xor_sync(0xffffffffu, key, j);
            int   ov = __shfl_xor_sync(0xffffffffu, val, j);
            bool keepMin = ((tid & k) == 0) == ((tid & j) == 0);
            bool take = keepMin ? (ok < key) : (ok > key);
            if (take) { key = ok; val = ov; }
        }
    }
    s.sdp[tid] = key; s.perm[tid] = val;
    __syncthreads();

    float dmax = s.sdp[511];
    float pv = __expf(key - dmax);
    float qv = __expf(ALPHA_ * (key - dmax));
    s.p2[tid] = pack2(pv, pv);
    s.q2[tid] = pack2(qv, qv);

    // exact inclusive scalar scans of p, q over 512
    float ip = pv, iq = qv;
#pragma unroll
    for (int off = 1; off < 32; off <<= 1) {
        float np = __shfl_up_sync(0xffffffffu, ip, off);
        float nq = __shfl_up_sync(0xffffffffu, iq, off);
        if (lane >= off) { ip += np; iq += nq; }
    }
    if (lane == 31) { s.wtP[wid] = ip; s.wtQ[wid] = iq; }
    __syncthreads();
    float offP = 0.f, offQ = 0.f;
    for (int w2 = 0; w2 < wid; w2++) { offP += s.wtP[w2]; offQ += s.wtQ[w2]; }
    s.Pp[tid] = ip + offP;
    s.Pq[tid] = iq + offQ;
    __syncthreads();

    // split point + per-query coefficients -> global
    {
        float ky = -s.ss[tid];
        int lo = 0, hi = 512;
        while (lo < hi) { int mid = (lo+hi) >> 1; if (s.sdp[mid] <= ky) lo = mid+1; else hi = mid; }
        float totS = s.Pp[511];
        float spx = lo ? s.Pp[lo-1] : 0.f;
        float sqx = lo ? s.Pq[lo-1] : 0.f;
        float spd = s.ss[tid] + dmax;
        float m   = spd > 0.f ? spd : ALPHA_*spd;
        float Af  = __expf(spd - m);
        float Bf  = __expf(ALPHA_*spd - m);
        float invZ = 1.f / (Af*(totS - spx) + Bf*sqx);
        g_coef[g*512 + tid] = make_float2(Af*invZ, Bf*invZ);
        g_kqg [g*512 + tid] = lo;
    }

    // gather permuted Wh rows as half2 channel pairs
    for (int j = wid; j < 512; j += 16) {
        float2 v = *(const float2*)&WhG[(size_t)s.perm[j]*64 + 2*lane];
        s.Whp[j*32 + lane] = __floats2half2_rn(v.x, v.y);
    }
    __syncthreads();

    // chunk sums (chunk = 16): warp w does chunks 2w, 2w+1
#pragma unroll
    for (int cc = 0; cc < 2; cc++) {
        int c = wid*2 + cc;
        ull aP = 0ull, aQ = 0ull;
#pragma unroll
        for (int t = 0; t < 16; t++) {
            int row = c*16 + t;
            float2 wf = __half22float2(s.Whp[row*32 + lane]);
            ull w2 = pack2(wf.x, wf.y);
            aP = ffma2(w2, s.p2[row], aP);
            aQ = ffma2(w2, s.q2[row], aQ);
        }
        s.cP2[c*32 + lane] = aP;
        s.cQ2[c*32 + lane] = aQ;
    }
    __syncthreads();

    // parallel inclusive Hillis-Steele scan over 32 chunks
    int e0 = tid, e1 = tid + 512;
    int c0e = e0 >> 5, c1e = e1 >> 5;
#pragma unroll
    for (int d = 1; d < 32; d <<= 1) {
        ull v0P = s.cP2[e0], v1P = s.cP2[e1];
        ull v0Q = s.cQ2[e0], v1Q = s.cQ2[e1];
        ull a0P = (c0e >= d) ? s.cP2[e0 - 32*d] : 0ull;
        ull a1P = (c1e >= d) ? s.cP2[e1 - 32*d] : 0ull;
        ull a0Q = (c0e >= d) ? s.cQ2[e0 - 32*d] : 0ull;
        ull a1Q = (c1e >= d) ? s.cQ2[e1 - 32*d] : 0ull;
        __syncthreads();
        s.cP2[e0] = add2(v0P, a0P); s.cP2[e1] = add2(v1P, a1P);
        s.cQ2[e0] = add2(v0Q, a0Q); s.cQ2[e1] = add2(v1Q, a1Q);
        __syncthreads();
    }
    // inclusive -> exclusive shift; [32] = totals
    {
        ull i0P = s.cP2[e0], i1P = s.cP2[e1];
        ull i0Q = s.cQ2[e0], i1Q = s.cQ2[e1];
        __syncthreads();
        s.cP2[e0 + 32] = i0P; s.cP2[e1 + 32] = i1P;
        s.cQ2[e0 + 32] = i0Q; s.cQ2[e1 + 32] = i1Q;
        if (tid < 32) { s.cP2[tid] = 0ull; s.cQ2[tid] = 0ull; }
        __syncthreads();
    }

    // expand full tables: thread = (chunk 0..15 x2, ch-pair). write SufP/PreQ.
    {
        int cp = tid & 31;
        float totPx, totPy, totQx, totQy;
        unpack2(s.cP2[32*32 + cp], totPx, totPy);
        unpack2(s.cQ2[32*32 + cp], totQx, totQy);
        float* tabS = g_tabS + (size_t)g*513*64;
        float* tabQ = g_tabQ + (size_t)g*513*64;
#pragma unroll
        for (int cc = 0; cc < 2; cc++) {
            int c = (tid >> 5) + cc*16;
            float rPx, rPy, rQx, rQy;
            unpack2(s.cP2[c*32 + cp], rPx, rPy);
            unpack2(s.cQ2[c*32 + cp], rQx, rQy);
#pragma unroll 4
            for (int r = 0; r < 16; r++) {
                int k = c*16 + r;
                *(float2*)&tabS[(size_t)k*64 + 2*cp] = make_float2(totPx - rPx, totPy - rPy);
                *(float2*)&tabQ[(size_t)k*64 + 2*cp] = make_float2(rQx, rQy);
                float2 wf = __half22float2(s.Whp[k*32 + cp]);
                float pvk, qvk, dum;
                unpack2(s.p2[k], pvk, dum);
                unpack2(s.q2[k], qvk, dum);
                rPx = fmaf(pvk, wf.x, rPx); rPy = fmaf(pvk, wf.y, rPy);
                rQx = fmaf(qvk, wf.x, rQx); rQy = fmaf(qvk, wf.y, rQy);
            }
        }
        if (tid < 32) {   // row 512: SufP = 0, PreQ = total
            *(float2*)&tabS[(size_t)512*64 + 2*cp] = make_float2(0.f, 0.f);
            *(float2*)&tabQ[(size_t)512*64 + 2*cp] = make_float2(totQx, totQy);
        }
    }
}

// =====================================================================
// attend_out: out[i,ch] = aC[i]*SufP[k_i][ch] + bC[i]*PreQ[k_i][ch]
// warp per query, lanes = 32 ch-pairs. No smem, high occupancy.
// =====================================================================
__global__ void attend_out(float* __restrict__ out,
                           int outBatch, int outHead, int rowStride,
                           int hPerB, int applyElu, int qSplit)
{
    int tid  = threadIdx.x;            // 512
    int lane = tid & 31, wid = tid >> 5;
    int g  = blockIdx.x / qSplit;
    int qo = blockIdx.x % qSplit;
    int b = g / hPerB, h = g % hPerB;

    const float* tabS = g_tabS + (size_t)g*513*64;
    const float* tabQ = g_tabQ + (size_t)g*513*64;
    float* outRow = out + (size_t)b*outBatch + (size_t)h*outHead;

    int qLen = 512 / qSplit;
    int itCount = qLen >> 4;
    int qBase = qo * qLen;
    for (int it = 0; it < itCount; it++) {
        int i = qBase + it*16 + wid;
        int kk = __ldg(&g_kqg[g*512 + i]);
        float2 cf = __ldg(&g_coef[g*512 + i]);
        float2 vS = __ldg((const float2*)&tabS[(size_t)kk*64 + 2*lane]);
        float2 vQ = __ldg((const float2*)&tabQ[(size_t)kk*64 + 2*lane]);
        float vx = cf.x*vS.x + cf.y*vQ.x;
        float vy = cf.x*vS.y + cf.y*vQ.y;
        if (applyElu) {
            vx = vx > 0.f ? vx : (__expf(vx) - 1.f);
            vy = vy > 0.f ? vy : (__expf(vy) - 1.f);
        }
        *(float2*)&outRow[(size_t)i*rowStride + 2*lane] = make_float2(vx, vy);
    }
}

// =====================================================================
// fc1 split-K, W staged through smem
// =====================================================================
__global__ void fc1_kernel(const float* __restrict__ W)
{
    __shared__ float z_s[32*40];
    __shared__ float w_s[32*64];
    int tid = threadIdx.x;       // 256
    int cb = blockIdx.x;         // 0..3
    int ks = blockIdx.y;         // 0..31
    int rg = tid >> 5;
    int cl = tid & 31;
    int c0 = cl*2;
    int kbase = ks*1024;

    ull a0[4], a1[4];
#pragma unroll
    for (int i = 0; i < 4; i++) { a0[i] = 0ull; a1[i] = 0ull; }

    for (int kk = 0; kk < 1024; kk += 32) {
#pragma unroll
        for (int t = 0; t < 4; t++) {
            int lin = t*256 + tid;
            int row = lin >> 5, k2 = lin & 31;
            z_s[row*40 + k2] = g_h2[(size_t)row*32768 + kbase + kk + k2];
        }
#pragma unroll
        for (int t = 0; t < 8; t++) {
            int lin = t*256 + tid;
            int k2 = lin >> 6, o = lin & 63;
            w_s[k2*64 + o] = W[(size_t)(kbase + kk + k2)*256 + cb*64 + o];
        }
        __syncthreads();
#pragma unroll 2
        for (int kq = 0; kq < 8; kq++) {
            float2 w0 = *(const float2*)&w_s[(4*kq+0)*64 + c0];
            float2 w1 = *(const float2*)&w_s[(4*kq+1)*64 + c0];
            float2 w2 = *(const float2*)&w_s[(4*kq+2)*64 + c0];
            float2 w3 = *(const float2*)&w_s[(4*kq+3)*64 + c0];
            ull wa0 = pack2(w0.x, w1.x), wa1 = pack2(w2.x, w3.x);
            ull wb0 = pack2(w0.y, w1.y), wb1 = pack2(w2.y, w3.y);
#pragma unroll
            for (int i = 0; i < 4; i++) {
                ulonglong2 zz = *(const ulonglong2*)&z_s[(rg*4+i)*40 + 4*kq];
                a0[i] = ffma2(zz.x, wa0, a0[i]);
                a1[i] = ffma2(zz.x, wb0, a1[i]);
                a0[i] = ffma2(zz.y, wa1, a0[i]);
                a1[i] = ffma2(zz.y, wb1, a1[i]);
            }
        }
        __syncthreads();
    }
#pragma unroll
    for (int i = 0; i < 4; i++) {
        g_z1p[(size_t)ks*8192 + (rg*4+i)*256 + cb*64 + c0    ] = pair_sum(a0[i]);
        g_z1p[(size_t)ks*8192 + (rg*4+i)*256 + cb*64 + c0 + 1] = pair_sum(a1[i]);
    }
}

// =====================================================================
// head: reduce fc1 partials + relu -> fc2 relu -> fc3 tanh
// =====================================================================
__global__ void head_kernel(const float* __restrict__ fc1_b,
                            const float* __restrict__ fc2_w,
                            const float* __restrict__ fc2_b,
                            const float* __restrict__ fc3_w,
                            const float* __restrict__ fc3_b,
                            float* __restrict__ out)
{
    __shared__ float z2[256], z3[256], red[256];
    int b = blockIdx.x, t = threadIdx.x;
    float v = fc1_b[t];
#pragma unroll
    for (int ks = 0; ks < 32; ks++) v += g_z1p[(size_t)ks*8192 + b*256 + t];
    z2[t] = v > 0.f ? v : 0.f;
    __syncthreads();
    float y = fc2_b[t];
#pragma unroll 8
    for (int k = 0; k < 256; k++) y += z2[k] * fc2_w[(size_t)k*256 + t];
    z3[t] = y > 0.f ? y : 0.f;
    __syncthreads();
    {
        int act = t & 3, grp = t >> 2;
        float partial = 0.f;
#pragma unroll
        for (int u = 0; u < 4; u++) {
            int k = grp*4 + u;
            partial += z3[k] * fc3_w[k*ACT_ + act];
        }
        red[t] = partial;
    }
    __syncthreads();
    if (t < ACT_) {
        float a = fc3_b[t];
#pragma unroll
        for (int j = 0; j < 64; j++) a += red[j*4 + t];
        out[b*ACT_ + t] = tanhf(a);
    }
}

// =====================================================================
extern "C" void kernel_launch(void* const* d_in, const int* in_sizes, int n_in,
                              void* d_out, int out_size)
{
    (void)in_sizes; (void)n_in; (void)out_size;
    const float* state     = (const float*)d_in[0];
    const float* W_heads   = (const float*)d_in[1];
    const float* a_src     = (const float*)d_in[2];
    const float* a_dst     = (const float*)d_in[3];
    const float* W_out     = (const float*)d_in[4];
    const float* a_out_src = (const float*)d_in[5];
    const float* a_out_dst = (const float*)d_in[6];
    const float* fc1_w     = (const float*)d_in[7];
    const float* fc1_b     = (const float*)d_in[8];
    const float* fc2_w     = (const float*)d_in[9];
    const float* fc2_b     = (const float*)d_in[10];
    const float* fc3_w     = (const float*)d_in[11];
    const float* fc3_b     = (const float*)d_in[12];
    float* out = (float*)d_out;

    float *pWh, *pss, *psd, *px, *pWh2, *ps2s, *ps2d, *ph2;
    cudaGetSymbolAddress((void**)&pWh,  g_Wh);
    cudaGetSymbolAddress((void**)&pss,  g_ssrc);
    cudaGetSymbolAddress((void**)&psd,  g_sdst);
    cudaGetSymbolAddress((void**)&px,   g_x);
    cudaGetSymbolAddress((void**)&pWh2, g_Wh2);
    cudaGetSymbolAddress((void**)&ps2s, g_s2s);
    cudaGetSymbolAddress((void**)&ps2d, g_s2d);
    cudaGetSymbolAddress((void**)&ph2,  g_h2);

    int attSmem = (int)sizeof(AttSmem);
    cudaFuncSetAttribute(attend_pre, cudaFuncAttributeMaxDynamicSharedMemorySize, attSmem);

    // Layer 1 GEMM (128-row tiles): 1024 blocks
    gemm_s_kernel<8><<<dim3(128, 8), 256>>>(state, W_heads, a_src, a_dst,
                                            pWh, pss, psd,
                                            64, H_*N_*64, N_*64, H_*N_);
    // Attend 1: preamble once per group, then streaming output + ELU
    attend_pre<<<256, 512, attSmem>>>(pWh, pss, psd);
    attend_out<<<512, 512>>>(px, N_*H_*64, 64, H_*64, H_, 1, 2);
    // Layer 2 GEMM (64-row tiles): 256 blocks
    gemm_s_kernel<4><<<dim3(256, 1), 256>>>(px, W_out, a_out_src, a_out_dst,
                                            pWh2, ps2s, ps2d,
                                            512, N_*64, 0, N_);
    // Attend 2
    attend_pre<<<32, 512, attSmem>>>(pWh2, ps2s, ps2d);
    attend_out<<<128, 512>>>(ph2, N_*64, 0, 64, 1, 0, 4);
    fc1_kernel<<<dim3(4, 32), 256>>>(fc1_w);
    head_kernel<<<32, 256>>>(fc1_b, fc2_w, fc2_b, fc3_w, fc3_b, out);
}